// round 6
// baseline (speedup 1.0000x reference)
#include <cuda_runtime.h>
#include <math.h>
#include <stdint.h>

#define BB 64
#define TT 512
#define DD 1024
#define HH 1024
#define HG 4096          // 4 gates * H

typedef unsigned long long ull;

// packed f32x2 fma: d = a*b + d  (elementwise on 2 fp32 lanes, bit-exact vs scalar)
__device__ __forceinline__ void ffma2(ull& d, ull a, ull b) {
    asm("fma.rn.f32x2 %0, %1, %2, %0;" : "+l"(d) : "l"(a), "l"(b));
}
__device__ __forceinline__ ull pack2(float lo, float hi) {
    ull r;
    asm("mov.b64 %0, {%1, %2};" : "=l"(r) : "f"(lo), "f"(hi));
    return r;
}
__device__ __forceinline__ void unpack2(float& lo, float& hi, ull v) {
    asm("mov.b64 {%0, %1}, %2;" : "=f"(lo), "=f"(hi) : "l"(v));
}

// ---------------- device scratch (no cudaMalloc allowed) ----------------
__device__ float g_Wx[DD * HG];                 // 16 MB  [k][gate*H+n] (gate-major)
__device__ float g_Whp[HH * HG];                // 16 MB  [k][packed col] gate-interleaved
__device__ float g_bias[HG];                    // folded b_i* + b_h*
__device__ float g_xact[(size_t)TT * BB * HG];  // 512 MB [t][b][packed col]
__device__ float g_h[BB * HH];                  // current hidden state
__device__ unsigned g_bar_count = 0;            // grid barrier
__device__ unsigned g_bar_gen = 0;

// packed col for (gate g, hidden n): CTA j=n>>3 owns n, cols [j*32, j*32+32)
// pc = (n>>3)*32 + (n&7)*4 + g  -> the 4 gates {i,f,g,o} of one n are one float4
__device__ __forceinline__ int pcol(int n) { return ((n >> 3) << 5) + ((n & 7) << 2); }

// ---------------- pack: permute weights, fold biases, zero state ----------------
__global__ void pack_kernel(
    const float* __restrict__ Wii, const float* __restrict__ Wif,
    const float* __restrict__ Wig, const float* __restrict__ Wio,
    const float* __restrict__ Whi, const float* __restrict__ Whf,
    const float* __restrict__ Whg, const float* __restrict__ Who,
    const float* __restrict__ bii, const float* __restrict__ bif,
    const float* __restrict__ big, const float* __restrict__ bio,
    const float* __restrict__ bhi, const float* __restrict__ bhf,
    const float* __restrict__ bhg, const float* __restrict__ bho)
{
    int gtid = blockIdx.x * blockDim.x + threadIdx.x;
    int stride = gridDim.x * blockDim.x;

    for (int idx = gtid; idx < DD * HH; idx += stride) {
        int k = idx >> 10;       // / H
        int n = idx & 1023;      // % H
        int base = k * HG + n;
        g_Wx[base + 0 * HH] = Wii[idx];
        g_Wx[base + 1 * HH] = Wif[idx];
        g_Wx[base + 2 * HH] = Wig[idx];
        g_Wx[base + 3 * HH] = Wio[idx];
        int pb = k * HG + pcol(n);
        g_Whp[pb + 0] = Whi[idx];
        g_Whp[pb + 1] = Whf[idx];
        g_Whp[pb + 2] = Whg[idx];
        g_Whp[pb + 3] = Who[idx];
    }
    for (int idx = gtid; idx < BB * HH; idx += stride)
        g_h[idx] = 0.0f;
    for (int idx = gtid; idx < HH; idx += stride) {
        g_bias[0 * HH + idx] = bii[idx] + bhi[idx];
        g_bias[1 * HH + idx] = bif[idx] + bhf[idx];
        g_bias[2 * HH + idx] = big[idx] + bhg[idx];
        g_bias[3 * HH + idx] = bio[idx] + bho[idx];
    }
}

// ---------------- phase 1: g_xact = x @ Wx + bias (packed layout) ----------------
#define BM 128
#define BN 128
#define BK 16

__global__ __launch_bounds__(256, 2)
void gemm_x_kernel(const float* __restrict__ X)
{
    __shared__ float xs[BK][BM];   // [k][m]
    __shared__ float ws[BK][BN];   // [k][n]

    const int m0 = blockIdx.y * BM;
    const int n0 = blockIdx.x * BN;
    const int tid = threadIdx.x;
    const int ty = tid >> 4;       // 0..15
    const int tx = tid & 15;       // 0..15

    ull acc2[8][4];                // 8 rows x 4 col-pairs, packed f32x2
    #pragma unroll
    for (int i = 0; i < 8; i++)
        #pragma unroll
        for (int j = 0; j < 4; j++) acc2[i][j] = 0ULL;

    for (int k0 = 0; k0 < DD; k0 += BK) {
        #pragma unroll
        for (int i = 0; i < 2; i++) {
            int idx = tid + i * 256;            // 0..511
            int row = idx >> 2;                 // 0..127
            int v = (idx & 3) * 4;              // 0,4,8,12
            float4 f = *(const float4*)(X + (size_t)(m0 + row) * DD + k0 + v);
            xs[v + 0][row] = f.x;
            xs[v + 1][row] = f.y;
            xs[v + 2][row] = f.z;
            xs[v + 3][row] = f.w;
        }
        #pragma unroll
        for (int i = 0; i < 2; i++) {
            int idx = tid + i * 256;            // 0..511
            int row = idx >> 5;                 // 0..15
            int vc = (idx & 31) * 4;            // 0..124
            *(float4*)&ws[row][vc] =
                *(const float4*)(g_Wx + (size_t)(k0 + row) * HG + n0 + vc);
        }
        __syncthreads();

        #pragma unroll
        for (int kk = 0; kk < BK; kk++) {
            ull ap[8], bp[4];
            #pragma unroll
            for (int i = 0; i < 8; i++) {
                float a = xs[kk][ty * 8 + i];
                ap[i] = pack2(a, a);
            }
            #pragma unroll
            for (int j = 0; j < 4; j++)
                bp[j] = *(const ull*)&ws[kk][tx * 8 + 2 * j];  // 8B-aligned
            #pragma unroll
            for (int i = 0; i < 8; i++)
                #pragma unroll
                for (int j = 0; j < 4; j++)
                    ffma2(acc2[i][j], ap[i], bp[j]);
        }
        __syncthreads();
    }

    // epilogue: add bias, write into packed [t][b][pc] layout
    #pragma unroll
    for (int i = 0; i < 8; i++) {
        int m = m0 + ty * 8 + i;   // m = b*T + t
        int b = m >> 9;            // / 512
        int t = m & 511;
        size_t rowbase = ((size_t)t * BB + b) * HG;
        float accf[8];
        #pragma unroll
        for (int j = 0; j < 4; j++)
            unpack2(accf[2 * j], accf[2 * j + 1], acc2[i][j]);
        #pragma unroll
        for (int j = 0; j < 8; j++) {
            int c = n0 + tx * 8 + j;          // original column (gate-major)
            int g = c >> 10;
            int n = c & 1023;
            g_xact[rowbase + pcol(n) + g] = accf[j] + g_bias[c];
        }
    }
}

// ---------------- software grid barrier (all 128 CTAs co-resident) ----------------
__device__ __forceinline__ void grid_sync_all()
{
    __threadfence();          // flush stores to GPU scope
    __syncthreads();
    if (threadIdx.x == 0) {
        unsigned gen = atomicAdd(&g_bar_gen, 0u);   // read gen BEFORE arriving
        unsigned arrived = atomicAdd(&g_bar_count, 1u);
        if (arrived == gridDim.x - 1) {
            g_bar_count = 0;
            __threadfence();
            atomicExch(&g_bar_gen, gen + 1u);
        } else {
            while (atomicAdd(&g_bar_gen, 0u) == gen) { __nanosleep(32); }
        }
        __threadfence();
    }
    __syncthreads();
}

// ---------------- persistent recurrence kernel ----------------
// 128 CTAs x 256 threads. CTA j owns n in [8j, 8j+8), all 4 gates, all 64 batches.
// Thread (u = tid&7, brow = tid>>3) owns (b=brow, n=8j+u) and (b=brow+32, n=8j+u).
// c lives in registers for all 512 steps. Gate-paired f32x2 FFMA.
#define PCTAS 128
#define KCHUNK 128
#define NTILE (HH / KCHUNK)     // 8
#define HS_STRIDE 66            // hs[k][66]: 64 batch slots (pairs) + 2 pad

__global__ __launch_bounds__(256, 1)
void lstm_persist_kernel(float* __restrict__ out)
{
    extern __shared__ float smem[];
    float* ws_all = smem;                       // [1024][32]  = 128 KB (Wh slice)
    float* hs = smem + HH * 32;                 // [128][66]   = 33 KB (h tile, transposed)

    const int j = blockIdx.x;
    const int tid = threadIdx.x;
    const int u = tid & 7;
    const int brow = tid >> 3;                  // 0..31

    // ---- load this CTA's Wh slice into smem (once) ----
    {
        const float4* src = (const float4*)(g_Whp);
        float4* dst = (float4*)ws_all;
        for (int i = tid; i < HH * 8; i += 256) {
            int k = i >> 3;
            int cc = i & 7;
            dst[k * 8 + cc] = src[(size_t)k * (HG / 4) + j * 8 + cc];
        }
    }
    __syncthreads();

    float creg[2] = {0.0f, 0.0f};
    const int ng = j * 8 + u;                   // global n owned by this thread

    // h-tile loader mapping: 8 float4 per thread per tile
    // it in [0, 2048): b = it>>5 (0..63), c4 = it&31 -> k offset c4*4
    float4 pf[8];

    for (int t = 0; t < TT; t++) {
        ull accif0 = 0ULL, accgo0 = 0ULL;       // batch brow:    {i,f} {g,o}
        ull accif1 = 0ULL, accgo1 = 0ULL;       // batch brow+32

        #pragma unroll 1
        for (int tile = 0; tile < NTILE; tile++) {
            __syncthreads();   // previous tile's hs readers done
            if (tile == 0) {
                #pragma unroll
                for (int r = 0; r < 8; r++) {
                    int it = tid + r * 256;
                    int b = it >> 5, c4 = it & 31;
                    pf[r] = __ldcg((const float4*)(g_h + b * HH + 0 * KCHUNK + c4 * 4));
                }
            }
            // store prefetched tile into hs, transposed: hs[k][2*(b&31) + (b>>5)]
            #pragma unroll
            for (int r = 0; r < 8; r++) {
                int it = tid + r * 256;
                int b = it >> 5, c4 = it & 31;
                int pos = 2 * (b & 31) + (b >> 5);
                int kb = c4 * 4;
                hs[(kb + 0) * HS_STRIDE + pos] = pf[r].x;
                hs[(kb + 1) * HS_STRIDE + pos] = pf[r].y;
                hs[(kb + 2) * HS_STRIDE + pos] = pf[r].z;
                hs[(kb + 3) * HS_STRIDE + pos] = pf[r].w;
            }
            // prefetch next tile (latency hidden under compute below)
            if (tile < NTILE - 1) {
                #pragma unroll
                for (int r = 0; r < 8; r++) {
                    int it = tid + r * 256;
                    int b = it >> 5, c4 = it & 31;
                    pf[r] = __ldcg((const float4*)(g_h + b * HH + (tile + 1) * KCHUNK + c4 * 4));
                }
            }
            __syncthreads();   // hs ready

            const int kw0 = tile * KCHUNK;
            #pragma unroll 8
            for (int kk = 0; kk < KCHUNK; kk++) {
                // weights: float4 {i,f,g,o} -> two packed f32x2 operands, zero pack cost
                ulonglong2 wv = *(const ulonglong2*)&ws_all[(kw0 + kk) * 32 + u * 4];
                // activations: {h[brow], h[brow+32]} adjacent -> one LDS.64
                ull a01 = *(const ull*)&hs[kk * HS_STRIDE + 2 * brow];
                float a0, a1;
                unpack2(a0, a1, a01);
                ull ap0 = pack2(a0, a0);
                ull ap1 = pack2(a1, a1);
                ffma2(accif0, ap0, wv.x);
                ffma2(accgo0, ap0, wv.y);
                ffma2(accif1, ap1, wv.x);
                ffma2(accgo1, ap1, wv.y);
            }
        }

        // ---- pointwise: gates -> c,h (c in registers) ----
        #pragma unroll
        for (int e = 0; e < 2; e++) {
            int b = brow + 32 * e;
            float si, sf, sg, so;
            if (e == 0) { unpack2(si, sf, accif0); unpack2(sg, so, accgo0); }
            else        { unpack2(si, sf, accif1); unpack2(sg, so, accgo1); }
            float4 xa = __ldcs((const float4*)(g_xact +
                         ((size_t)t * BB + b) * HG + j * 32 + u * 4));
            float pi = si + xa.x;
            float pf_ = sf + xa.y;
            float pg = sg + xa.z;
            float po = so + xa.w;

            float it_ = 1.0f / (1.0f + expf(-pi));
            float ft = 1.0f / (1.0f + expf(-pf_));
            float gt = tanhf(pg);
            float ot = 1.0f / (1.0f + expf(-po));

            float c = ft * creg[e] + it_ * gt;
            float h = ot * tanhf(c);
            creg[e] = c;

            g_h[b * HH + ng] = h;
            out[((size_t)b * TT + t) * HH + ng] = h;
        }

        grid_sync_all();   // h fully updated before any CTA starts step t+1
    }
}

// ---------------- launch ----------------
extern "C" void kernel_launch(void* const* d_in, const int* in_sizes, int n_in,
                              void* d_out, int out_size)
{
    const float* x   = (const float*)d_in[0];
    const float* Wii = (const float*)d_in[1];
    const float* bii = (const float*)d_in[2];
    const float* Whi = (const float*)d_in[3];
    const float* bhi = (const float*)d_in[4];
    const float* Wif = (const float*)d_in[5];
    const float* bif = (const float*)d_in[6];
    const float* Whf = (const float*)d_in[7];
    const float* bhf = (const float*)d_in[8];
    const float* Wig = (const float*)d_in[9];
    const float* big = (const float*)d_in[10];
    const float* Whg = (const float*)d_in[11];
    const float* bhg = (const float*)d_in[12];
    const float* Wio = (const float*)d_in[13];
    const float* bio = (const float*)d_in[14];
    const float* Who = (const float*)d_in[15];
    const float* bho = (const float*)d_in[16];
    float* out = (float*)d_out;

    pack_kernel<<<512, 256>>>(Wii, Wif, Wig, Wio, Whi, Whf, Whg, Who,
                              bii, bif, big, bio, bhi, bhf, bhg, bho);

    // phase 1: (32768 x 4096) = X (32768 x 1024) @ Wx (1024 x 4096)
    gemm_x_kernel<<<dim3(HG / BN, (BB * TT) / BM), 256>>>(x);

    // phase 2: single persistent kernel for all 512 steps
    const int smem_bytes = (HH * 32 + KCHUNK * HS_STRIDE) * (int)sizeof(float); // ~165 KB
    cudaFuncSetAttribute(lstm_persist_kernel,
                         cudaFuncAttributeMaxDynamicSharedMemorySize, smem_bytes);
    lstm_persist_kernel<<<PCTAS, 256, smem_bytes>>>(out);
}